// round 6
// baseline (speedup 1.0000x reference)
#include <cuda_runtime.h>
#include <math.h>

// ---------------- constants ----------------
#define PREF   138.935456f
#define ALPHA  3.0f
#define CUT2   0.81f          // 0.9^2
#define CULL2  0.8190f        // (0.9 + safety)^2 for conservative tile culling
#define MAXH   8
#define NHK    145            // half k-space (h,k) blocks: 8*17 + 8 + 1
#define NSF    (NHK * 17)     // 2465 stored structure factors

#define ITILE 128
#define JHALF 64
#define MAXN  8192
#define MAXT  (MAXN / ITILE)

__device__ float4 g_atoms[MAXN];   // x,y,z,charge (padded with q=0 copies of last atom)
__device__ float4 g_tbox[MAXT];    // per-tile (cx, hx, cy, hy)
__device__ float2 g_S[NSF];        // structure factors (re, im)
__device__ double g_energy;

// ---------------- reductions ----------------
__device__ __forceinline__ double blockReduceD(double v) {
    __shared__ double sh[32];
    int lane = threadIdx.x & 31;
    int wid  = threadIdx.x >> 5;
#pragma unroll
    for (int o = 16; o > 0; o >>= 1) v += __shfl_down_sync(0xffffffffu, v, o);
    if (lane == 0) sh[wid] = v;
    __syncthreads();
    int nwarp = (blockDim.x + 31) >> 5;
    v = (threadIdx.x < nwarp) ? sh[threadIdx.x] : 0.0;
    if (wid == 0) {
#pragma unroll
        for (int o = 16; o > 0; o >>= 1) v += __shfl_down_sync(0xffffffffu, v, o);
    }
    return v;
}

__device__ __forceinline__ float mic(float d, float L, float invL) {
    return d - L * rintf(d * invL);   // round-half-even, matches jnp.round
}

// (h,k) decode for the half k-space block list
__device__ __forceinline__ void hk_decode(int hk, int &h, int &k) {
    if (hk < 136)      { h = hk / 17 - 8; k = hk % 17 - 8; }  // h = -8..-1, all k
    else if (hk < 144) { h = 0; k = hk - 144; }               // h = 0, k = -8..-1
    else               { h = 0; k = 0; }                      // l < 0 only
}

// ---------------- kernel 1: init (zero accum + S, pack + pad atoms) ----------------
__global__ void k_init(const float* __restrict__ coords,
                       const float* __restrict__ charges, int N, int ntot) {
    int i = blockIdx.x * blockDim.x + threadIdx.x;
    if (i == 0) g_energy = 0.0;
    if (i < N) {
        g_atoms[i] = make_float4(coords[3*i], coords[3*i+1], coords[3*i+2], charges[i]);
    } else if (i < ntot) {
        // pad with last real atom's coords (keeps tile bbox tight), q = 0
        g_atoms[i] = make_float4(coords[3*(N-1)], coords[3*(N-1)+1], coords[3*(N-1)+2], 0.0f);
    }
    if (i < NSF) g_S[i] = make_float2(0.0f, 0.0f);
}

// ---------------- kernel 1b: per-tile AABB in x,y ----------------
__global__ void k_tiles() {
    int i = blockIdx.x * ITILE + threadIdx.x;   // exactly one atom per thread
    float4 a = g_atoms[i];
    float mnx = a.x, mxx = a.x, mny = a.y, mxy = a.y;
    int lane = threadIdx.x & 31;
    int wid  = threadIdx.x >> 5;
#pragma unroll
    for (int o = 16; o > 0; o >>= 1) {
        mnx = fminf(mnx, __shfl_down_sync(0xffffffffu, mnx, o));
        mxx = fmaxf(mxx, __shfl_down_sync(0xffffffffu, mxx, o));
        mny = fminf(mny, __shfl_down_sync(0xffffffffu, mny, o));
        mxy = fmaxf(mxy, __shfl_down_sync(0xffffffffu, mxy, o));
    }
    __shared__ float s0[4], s1[4], s2[4], s3[4];
    if (lane == 0) { s0[wid] = mnx; s1[wid] = mxx; s2[wid] = mny; s3[wid] = mxy; }
    __syncthreads();
    if (threadIdx.x == 0) {
        mnx = fminf(fminf(s0[0], s0[1]), fminf(s0[2], s0[3]));
        mxx = fmaxf(fmaxf(s1[0], s1[1]), fmaxf(s1[2], s1[3]));
        mny = fminf(fminf(s2[0], s2[1]), fminf(s2[2], s2[3]));
        mxy = fmaxf(fmaxf(s3[0], s3[1]), fmaxf(s3[2], s3[3]));
        g_tbox[blockIdx.x] = make_float4(0.5f * (mnx + mxx), 0.5f * (mxx - mnx),
                                         0.5f * (mny + mxy), 0.5f * (mxy - mny));
    }
}

// ---------------- kernel 2: bonded + angles + full-Coulomb excl + self ----------------
// k_pair includes intra-molecular pairs with erfc; combined with the reference's
// -qq*erf/r exclusion term this collapses to -qq/r (erf + erfc = 1).
__global__ void k_bonded(const float* __restrict__ coords,
                         const float* __restrict__ box,
                         const int*   __restrict__ bonds,
                         const float* __restrict__ b0,
                         const float* __restrict__ kb, int nb,
                         const int*   __restrict__ angles,
                         const float* __restrict__ th0,
                         const float* __restrict__ kth, int na,
                         const int*   __restrict__ cex,
                         const float* __restrict__ charges, int nex, int N) {
    const float Lx = box[0], Ly = box[1], Lz = box[2];
    const float iLx = 1.0f/Lx, iLy = 1.0f/Ly, iLz = 1.0f/Lz;
    int i = blockIdx.x * blockDim.x + threadIdx.x;
    double e = 0.0;

    if (i < nb) {
        int a = bonds[2*i], b = bonds[2*i+1];
        float dx = mic(coords[3*a+0]-coords[3*b+0], Lx, iLx);
        float dy = mic(coords[3*a+1]-coords[3*b+1], Ly, iLy);
        float dz = mic(coords[3*a+2]-coords[3*b+2], Lz, iLz);
        float r = sqrtf(dx*dx + dy*dy + dz*dz);
        float d = r - b0[i];
        e += 0.5 * (double)(kb[i] * d * d);
    }
    if (i < na) {
        int a0 = angles[3*i], a1 = angles[3*i+1], a2 = angles[3*i+2];
        float v1x = mic(coords[3*a0+0]-coords[3*a1+0], Lx, iLx);
        float v1y = mic(coords[3*a0+1]-coords[3*a1+1], Ly, iLy);
        float v1z = mic(coords[3*a0+2]-coords[3*a1+2], Lz, iLz);
        float v2x = mic(coords[3*a2+0]-coords[3*a1+0], Lx, iLx);
        float v2y = mic(coords[3*a2+1]-coords[3*a1+1], Ly, iLy);
        float v2z = mic(coords[3*a2+2]-coords[3*a1+2], Lz, iLz);
        float n1 = sqrtf(v1x*v1x + v1y*v1y + v1z*v1z);
        float n2 = sqrtf(v2x*v2x + v2y*v2y + v2z*v2z);
        float ct = (v1x*v2x + v1y*v2y + v1z*v2z) / (n1 * n2);
        ct = fminf(fmaxf(ct, -1.0f + 1e-7f), 1.0f - 1e-7f);
        float th = acosf(ct);
        float d = th - th0[i];
        e += 0.5 * (double)(kth[i] * d * d);
    }
    if (i < nex) {   // -PREF * q_a q_b / r   (erf + erfc merged)
        int a = cex[2*i], b = cex[2*i+1];
        float dx = mic(coords[3*a+0]-coords[3*b+0], Lx, iLx);
        float dy = mic(coords[3*a+1]-coords[3*b+1], Ly, iLy);
        float dz = mic(coords[3*a+2]-coords[3*b+2], Lz, iLz);
        float r = sqrtf(dx*dx + dy*dy + dz*dz);
        float qx = charges[a] * charges[b];
        e -= (double)(PREF * qx / r);
    }
    if (i < N) {     // self: -PREF * alpha/sqrt(pi) * q^2
        float q = charges[i];
        e -= (double)(PREF * (ALPHA * 0.5641895835477563f) * q * q);
    }

    double s = blockReduceD(e);
    if (threadIdx.x == 0 && s != 0.0) atomicAdd(&g_energy, s);
}

// ---------------- kernel 3: real-space nonbonded ----------------
// Triangular 128x128 tile pairs; 128 threads (1 i-atom each); j-tile split in
// two 64-atom halves over blockIdx.y. Tile-pair AABB culling with early exit.
// Intra-molecular pairs included (corrected exactly in k_bonded).
__device__ __forceinline__ int row_start(int ti, int nt) {
    return ti * (2 * nt - ti + 1) / 2;
}

__device__ __forceinline__ void pair_term(
    float4 a, bool iO, float4 b, bool take,
    float Lx, float Ly, float Lz, float iLx, float iLy, float iLz,
    float s00sq, float e00x4, float &ec, float &el)
{
    float dx = mic(a.x - b.x, Lx, iLx);
    float dy = mic(a.y - b.y, Ly, iLy);
    float dz = mic(a.z - b.z, Lz, iLz);
    float r2 = fmaf(dx, dx, fmaf(dy, dy, dz * dz));
    r2 = fmaxf(r2, 1e-6f);                      // guards padded-atom r2=0
    if (take && r2 < CUT2) {
        float rinv = rsqrtf(r2);
        float x    = ALPHA * r2 * rinv;          // alpha * r
        // erfc(x) via A&S 7.1.26 (|abs err| <= 1.5e-7)
        float tt = __fdividef(1.0f, fmaf(0.3275911f, x, 1.0f));
        float p  = fmaf(1.061405429f, tt, -1.453152027f);
        p = fmaf(p, tt, 1.421413741f);
        p = fmaf(p, tt, -0.284496736f);
        p = fmaf(p, tt, 0.254829592f);
        p = p * tt;
        float ef = p * __expf(-x * x);
        ec = fmaf(a.w * b.w, ef * rinv, ec);
        float eps4 = (iO && b.w < 0.0f) ? e00x4 : 0.0f;   // O-O only
        float sr2  = s00sq * (rinv * rinv);
        float s6   = sr2 * sr2 * sr2;
        el = fmaf(eps4, s6 * s6 - s6, el);
    }
}

__global__ void k_pair(int nt, const float* __restrict__ box,
                       const float* __restrict__ sigma,
                       const float* __restrict__ epsilon) {
    // decode triangular block index -> (ti, tj), ti <= tj
    int b = blockIdx.x;
    float nt2 = 2.0f * nt + 1.0f;
    int ti = (int)((nt2 - sqrtf(nt2 * nt2 - 8.0f * (float)b)) * 0.5f);
    if (ti < 0) ti = 0;
    while (ti + 1 < nt && row_start(ti + 1, nt) <= b) ti++;
    while (ti > 0 && row_start(ti, nt) > b) ti--;
    int tj = ti + (b - row_start(ti, nt));

    const float Lx = box[0], Ly = box[1], Lz = box[2];
    const float iLx = 1.0f/Lx, iLy = 1.0f/Ly, iLz = 1.0f/Lz;

    // ---- tile-pair AABB cull (uniform across block, before any sync) ----
    if (ti != tj) {
        float4 bi = g_tbox[ti];
        float4 bj = g_tbox[tj];
        float dxm = fmaxf(fabsf(mic(bi.x - bj.x, Lx, iLx)) - (bi.y + bj.y), 0.0f);
        float dym = fmaxf(fabsf(mic(bi.z - bj.z, Ly, iLy)) - (bi.w + bj.w), 0.0f);
        if (fmaf(dxm, dxm, dym * dym) >= CULL2) return;
    }

    const float s00sq = sigma[0] * sigma[0];
    const float e00x4 = 4.0f * epsilon[0];

    __shared__ float4 sj[JHALF];
    int jbase = tj * ITILE + blockIdx.y * JHALF;
    if ((int)threadIdx.x < JHALF) sj[threadIdx.x] = g_atoms[jbase + threadIdx.x];
    __syncthreads();

    int i = ti * ITILE + threadIdx.x;
    float4 a = g_atoms[i];
    bool iO = (a.w < 0.0f);

    float ec = 0.0f, el = 0.0f;
    if (ti == tj) {
#pragma unroll 8
        for (int t = 0; t < JHALF; ++t) {
            int j = jbase + t;
            pair_term(a, iO, sj[t], j > i, Lx, Ly, Lz, iLx, iLy, iLz, s00sq, e00x4, ec, el);
        }
    } else {
#pragma unroll 8
        for (int t = 0; t < JHALF; ++t) {
            pair_term(a, iO, sj[t], true, Lx, Ly, Lz, iLx, iLy, iLz, s00sq, e00x4, ec, el);
        }
    }

    double e = (double)PREF * (double)ec + (double)el;
    double s = blockReduceD(e);
    if (threadIdx.x == 0 && s != 0.0) atomicAdd(&g_energy, s);
}

// ---------------- kernel 4: structure factors, half k-space ----------------
// grid (NHK, NCHUNK); block 128. Each block: one (h,k), one atom chunk, all
// 17 l via complex rotation. Two independent rotation chains per thread (ILP).
#define RT_THREADS 128
#define NCHUNK 16

__global__ void k_recip(int N, int CH, const float* __restrict__ box) {
    int hk = blockIdx.x;
    int h, k; hk_decode(hk, h, k);

    const float Lx = box[0], Ly = box[1], Lz = box[2];
    const float twopi = 6.283185307179586f;
    const float gz = twopi / Lz;
    const float kx = twopi * (float)h / Lx;
    const float ky = twopi * (float)k / Ly;

    int base = blockIdx.y * CH;
    int end  = min(N, base + CH);

    float accR[17], accI[17];
#pragma unroll
    for (int l = 0; l < 17; ++l) { accR[l] = 0.0f; accI[l] = 0.0f; }

    for (int i = base + threadIdx.x; i < end; i += 2 * RT_THREADS) {
        float4 a1 = g_atoms[i];
        int ii = i + RT_THREADS;
        float4 a2 = (ii < end) ? g_atoms[ii] : make_float4(0.f, 0.f, 0.f, 0.f);

        float phz1 = gz * a1.z, phz2 = gz * a2.z;
        float s1, c1, d1s, d1c, s2, c2, d2s, d2c;
        sincosf(kx * a1.x + ky * a1.y - 8.0f * phz1, &s1, &c1);
        sincosf(phz1, &d1s, &d1c);
        sincosf(kx * a2.x + ky * a2.y - 8.0f * phz2, &s2, &c2);
        sincosf(phz2, &d2s, &d2c);
        float q1 = a1.w, q2 = a2.w;
#pragma unroll
        for (int l = 0; l < 17; ++l) {
            accR[l] = fmaf(q1, c1, fmaf(q2, c2, accR[l]));
            accI[l] = fmaf(q1, s1, fmaf(q2, s2, accI[l]));
            float n1 = c1 * d1c - s1 * d1s;
            s1 = fmaf(s1, d1c, c1 * d1s); c1 = n1;
            float n2 = c2 * d2c - s2 * d2s;
            s2 = fmaf(s2, d2c, c2 * d2s); c2 = n2;
        }
    }

    // block reduction: warp shuffle then cross-warp, then float atomics to g_S
    __shared__ float shR[RT_THREADS / 32][17], shI[RT_THREADS / 32][17];
    int lane = threadIdx.x & 31;
    int wid  = threadIdx.x >> 5;
#pragma unroll
    for (int l = 0; l < 17; ++l) {
        float r = accR[l], im = accI[l];
#pragma unroll
        for (int o = 16; o > 0; o >>= 1) {
            r  += __shfl_down_sync(0xffffffffu, r,  o);
            im += __shfl_down_sync(0xffffffffu, im, o);
        }
        if (lane == 0) { shR[wid][l] = r; shI[wid][l] = im; }
    }
    __syncthreads();
    if (threadIdx.x < 17) {
        int l = threadIdx.x;
        float R = 0.0f, I = 0.0f;
#pragma unroll
        for (int w = 0; w < RT_THREADS / 32; ++w) { R += shR[w][l]; I += shI[w][l]; }
        atomicAdd(&g_S[hk * 17 + l].x, R);
        atomicAdd(&g_S[hk * 17 + l].y, I);
    }
}

// ---------------- kernel 5: reciprocal energy from S ----------------
__global__ void k_recipE(const float* __restrict__ box) {
    const float Lx = box[0], Ly = box[1], Lz = box[2];
    const double gx = 2.0 * 3.141592653589793 / (double)Lx;
    const double gy = 2.0 * 3.141592653589793 / (double)Ly;
    const double gzd = 2.0 * 3.141592653589793 / (double)Lz;
    double e = 0.0;
    for (int idx = threadIdx.x; idx < NSF; idx += blockDim.x) {
        int hk = idx / 17;
        int l  = idx % 17 - 8;
        int h, k; hk_decode(hk, h, k);
        if (h == 0 && k == 0 && l >= 0) continue;   // k=0 excluded; l>0 via conj
        float2 S = g_S[idx];
        double kxd = gx * h, kyd = gy * k, kzd = gzd * l;
        double k2 = kxd * kxd + kyd * kyd + kzd * kzd;
        double w  = exp(-k2 / 36.0) / k2;           // 4*alpha^2 = 36
        e += 2.0 * w * ((double)S.x * S.x + (double)S.y * S.y);  // x2: +-k pair
    }
    double V = (double)Lx * (double)Ly * (double)Lz;
    e *= (double)PREF * (2.0 * 3.141592653589793 / V);
    double s = blockReduceD(e);
    if (threadIdx.x == 0) atomicAdd(&g_energy, s);
}

// ---------------- kernel 6: finalize ----------------
__global__ void k_final(float* out) {
    out[0] = (float)g_energy;
}

// ---------------- launch ----------------
extern "C" void kernel_launch(void* const* d_in, const int* in_sizes, int n_in,
                              void* d_out, int out_size) {
    const float* coords  = (const float*)d_in[0];
    const float* box     = (const float*)d_in[1];
    const int*   bonds   = (const int*)  d_in[2];
    const float* b0      = (const float*)d_in[3];
    const float* kb      = (const float*)d_in[4];
    const int*   angles  = (const int*)  d_in[5];
    const float* th0     = (const float*)d_in[6];
    const float* kth     = (const float*)d_in[7];
    const float* charges = (const float*)d_in[8];
    const float* sigma   = (const float*)d_in[9];
    const float* epsilon = (const float*)d_in[10];
    const int*   cex     = (const int*)  d_in[13];   // coulomb_excl_pairs

    int N   = in_sizes[0] / 3;
    int nb  = in_sizes[2] / 2;
    int na  = in_sizes[5] / 3;
    int nex = in_sizes[13] / 2;

    float* out = (float*)d_out;

    int nt   = (N + ITILE - 1) / ITILE;
    int ntot = nt * ITILE;

    int nthr = 256;
    int initWork = (ntot > NSF) ? ntot : NSF;
    int maxWork = N;
    if (nb  > maxWork) maxWork = nb;
    if (na  > maxWork) maxWork = na;
    if (nex > maxWork) maxWork = nex;

    k_init<<<(initWork + nthr - 1) / nthr, nthr>>>(coords, charges, N, ntot);
    k_tiles<<<nt, ITILE>>>();
    k_bonded<<<(maxWork + nthr - 1) / nthr, nthr>>>(coords, box, bonds, b0, kb, nb,
                                                    angles, th0, kth, na,
                                                    cex, charges, nex, N);
    dim3 pg(nt * (nt + 1) / 2, ITILE / JHALF);
    k_pair<<<pg, ITILE>>>(nt, box, sigma, epsilon);

    int CH = (N + NCHUNK - 1) / NCHUNK;
    dim3 rg(NHK, NCHUNK);
    k_recip<<<rg, RT_THREADS>>>(N, CH, box);
    k_recipE<<<1, 256>>>(box);
    k_final<<<1, 1>>>(out);
}

// round 7
// speedup vs baseline: 1.7201x; 1.7201x over previous
#include <cuda_runtime.h>
#include <math.h>

// ---------------- constants ----------------
#define PREF   138.935456f
#define ALPHA  3.0f
#define CUT2   0.81f          // 0.9^2
#define CULL2  0.8190f        // (0.9 + safety)^2 for conservative tile culling
#define MAXH   8
#define NHK    145            // half k-space (h,k) blocks: 8*17 + 8 + 1
#define NSF    (NHK * 17)     // 2465 stored structure factors

#define ITILE 128
#define JHALF 64
#define MAXN  8192
#define MAXT  (MAXN / ITILE)

__device__ float4 g_atoms[MAXN];   // x,y,z,charge (padded with q=0 copies of last atom)
__device__ float4 g_tbox[MAXT];    // per-tile (cx, hx, cy, hy)
__device__ float2 g_S[NSF];        // structure factors (re, im)
__device__ double g_energy;

// ---------------- reductions ----------------
__device__ __forceinline__ double blockReduceD(double v) {
    __shared__ double sh[32];
    int lane = threadIdx.x & 31;
    int wid  = threadIdx.x >> 5;
#pragma unroll
    for (int o = 16; o > 0; o >>= 1) v += __shfl_down_sync(0xffffffffu, v, o);
    if (lane == 0) sh[wid] = v;
    __syncthreads();
    int nwarp = (blockDim.x + 31) >> 5;
    v = (threadIdx.x < nwarp) ? sh[threadIdx.x] : 0.0;
    if (wid == 0) {
#pragma unroll
        for (int o = 16; o > 0; o >>= 1) v += __shfl_down_sync(0xffffffffu, v, o);
    }
    return v;
}

__device__ __forceinline__ float mic(float d, float L, float invL) {
    return d - L * rintf(d * invL);   // round-half-even, matches jnp.round
}

// (h,k) decode for the half k-space block list
__device__ __forceinline__ void hk_decode(int hk, int &h, int &k) {
    if (hk < 136)      { h = hk / 17 - 8; k = hk % 17 - 8; }  // h = -8..-1, all k
    else if (hk < 144) { h = 0; k = hk - 144; }               // h = 0, k = -8..-1
    else               { h = 0; k = 0; }                      // l < 0 only
}

// ---------------- kernel 1: prep (pack+pad atoms, tile bbox, zero accums) ----------------
// grid = nt blocks of ITILE threads; block b owns atoms [b*128, (b+1)*128).
__global__ void k_prep(const float* __restrict__ coords,
                       const float* __restrict__ charges, int N, int nt) {
    int i = blockIdx.x * ITILE + threadIdx.x;
    int gid = i;
    if (gid == 0) g_energy = 0.0;
    for (int s = gid; s < NSF; s += nt * ITILE) g_S[s] = make_float2(0.0f, 0.0f);

    float4 a;
    if (i < N) a = make_float4(coords[3*i], coords[3*i+1], coords[3*i+2], charges[i]);
    else       a = make_float4(coords[3*(N-1)], coords[3*(N-1)+1], coords[3*(N-1)+2], 0.0f);
    g_atoms[i] = a;

    // tile AABB in x,y
    float mnx = a.x, mxx = a.x, mny = a.y, mxy = a.y;
    int lane = threadIdx.x & 31;
    int wid  = threadIdx.x >> 5;
#pragma unroll
    for (int o = 16; o > 0; o >>= 1) {
        mnx = fminf(mnx, __shfl_down_sync(0xffffffffu, mnx, o));
        mxx = fmaxf(mxx, __shfl_down_sync(0xffffffffu, mxx, o));
        mny = fminf(mny, __shfl_down_sync(0xffffffffu, mny, o));
        mxy = fmaxf(mxy, __shfl_down_sync(0xffffffffu, mxy, o));
    }
    __shared__ float s0[4], s1[4], s2[4], s3[4];
    if (lane == 0) { s0[wid] = mnx; s1[wid] = mxx; s2[wid] = mny; s3[wid] = mxy; }
    __syncthreads();
    if (threadIdx.x == 0) {
        mnx = fminf(fminf(s0[0], s0[1]), fminf(s0[2], s0[3]));
        mxx = fmaxf(fmaxf(s1[0], s1[1]), fmaxf(s1[2], s1[3]));
        mny = fminf(fminf(s2[0], s2[1]), fminf(s2[2], s2[3]));
        mxy = fmaxf(fmaxf(s3[0], s3[1]), fmaxf(s3[2], s3[3]));
        g_tbox[blockIdx.x] = make_float4(0.5f * (mnx + mxx), 0.5f * (mxx - mnx),
                                         0.5f * (mny + mxy), 0.5f * (mxy - mny));
    }
}

// ---------------- kernel 2: bonded + angles + full-Coulomb excl + self ----------------
// k_pair includes intra-molecular pairs with erfc; combined with the reference's
// -qq*erf/r exclusion term this collapses to -qq/r (erf + erfc = 1).
__global__ void k_bonded(const float* __restrict__ coords,
                         const float* __restrict__ box,
                         const int*   __restrict__ bonds,
                         const float* __restrict__ b0,
                         const float* __restrict__ kb, int nb,
                         const int*   __restrict__ angles,
                         const float* __restrict__ th0,
                         const float* __restrict__ kth, int na,
                         const int*   __restrict__ cex,
                         const float* __restrict__ charges, int nex, int N) {
    const float Lx = box[0], Ly = box[1], Lz = box[2];
    const float iLx = 1.0f/Lx, iLy = 1.0f/Ly, iLz = 1.0f/Lz;
    int i = blockIdx.x * blockDim.x + threadIdx.x;
    double e = 0.0;

    if (i < nb) {
        int a = bonds[2*i], b = bonds[2*i+1];
        float dx = mic(coords[3*a+0]-coords[3*b+0], Lx, iLx);
        float dy = mic(coords[3*a+1]-coords[3*b+1], Ly, iLy);
        float dz = mic(coords[3*a+2]-coords[3*b+2], Lz, iLz);
        float r = sqrtf(dx*dx + dy*dy + dz*dz);
        float d = r - b0[i];
        e += 0.5 * (double)(kb[i] * d * d);
    }
    if (i < na) {
        int a0 = angles[3*i], a1 = angles[3*i+1], a2 = angles[3*i+2];
        float v1x = mic(coords[3*a0+0]-coords[3*a1+0], Lx, iLx);
        float v1y = mic(coords[3*a0+1]-coords[3*a1+1], Ly, iLy);
        float v1z = mic(coords[3*a0+2]-coords[3*a1+2], Lz, iLz);
        float v2x = mic(coords[3*a2+0]-coords[3*a1+0], Lx, iLx);
        float v2y = mic(coords[3*a2+1]-coords[3*a1+1], Ly, iLy);
        float v2z = mic(coords[3*a2+2]-coords[3*a1+2], Lz, iLz);
        float n1 = sqrtf(v1x*v1x + v1y*v1y + v1z*v1z);
        float n2 = sqrtf(v2x*v2x + v2y*v2y + v2z*v2z);
        float ct = (v1x*v2x + v1y*v2y + v1z*v2z) / (n1 * n2);
        ct = fminf(fmaxf(ct, -1.0f + 1e-7f), 1.0f - 1e-7f);
        float th = acosf(ct);
        float d = th - th0[i];
        e += 0.5 * (double)(kth[i] * d * d);
    }
    if (i < nex) {   // -PREF * q_a q_b / r   (erf + erfc merged)
        int a = cex[2*i], b = cex[2*i+1];
        float dx = mic(coords[3*a+0]-coords[3*b+0], Lx, iLx);
        float dy = mic(coords[3*a+1]-coords[3*b+1], Ly, iLy);
        float dz = mic(coords[3*a+2]-coords[3*b+2], Lz, iLz);
        float r = sqrtf(dx*dx + dy*dy + dz*dz);
        float qx = charges[a] * charges[b];
        e -= (double)(PREF * qx / r);
    }
    if (i < N) {     // self: -PREF * alpha/sqrt(pi) * q^2
        float q = charges[i];
        e -= (double)(PREF * (ALPHA * 0.5641895835477563f) * q * q);
    }

    double s = blockReduceD(e);
    if (threadIdx.x == 0 && s != 0.0) atomicAdd(&g_energy, s);
}

// ---------------- kernel 3: real-space nonbonded ----------------
// Triangular 128x128 tile pairs; 128 threads (1 i-atom each); j-tile split in
// two 64-atom halves over blockIdx.y. Tile-pair AABB culling with early exit.
__device__ __forceinline__ int row_start(int ti, int nt) {
    return ti * (2 * nt - ti + 1) / 2;
}

__device__ __forceinline__ void pair_term(
    float4 a, bool iO, float4 b, bool take,
    float Lx, float Ly, float Lz, float iLx, float iLy, float iLz,
    float s00sq, float e00x4, float &ec, float &el)
{
    float dx = mic(a.x - b.x, Lx, iLx);
    float dy = mic(a.y - b.y, Ly, iLy);
    float dz = mic(a.z - b.z, Lz, iLz);
    float r2 = fmaf(dx, dx, fmaf(dy, dy, dz * dz));
    r2 = fmaxf(r2, 1e-6f);                      // guards padded-atom r2=0
    if (take && r2 < CUT2) {
        float rinv = rsqrtf(r2);
        float x    = ALPHA * r2 * rinv;          // alpha * r
        // erfc(x) via A&S 7.1.26 (|abs err| <= 1.5e-7)
        float tt = __fdividef(1.0f, fmaf(0.3275911f, x, 1.0f));
        float p  = fmaf(1.061405429f, tt, -1.453152027f);
        p = fmaf(p, tt, 1.421413741f);
        p = fmaf(p, tt, -0.284496736f);
        p = fmaf(p, tt, 0.254829592f);
        p = p * tt;
        float ef = p * __expf(-x * x);
        ec = fmaf(a.w * b.w, ef * rinv, ec);
        float eps4 = (iO && b.w < 0.0f) ? e00x4 : 0.0f;   // O-O only
        float sr2  = s00sq * (rinv * rinv);
        float s6   = sr2 * sr2 * sr2;
        el = fmaf(eps4, s6 * s6 - s6, el);
    }
}

__global__ void k_pair(int nt, const float* __restrict__ box,
                       const float* __restrict__ sigma,
                       const float* __restrict__ epsilon) {
    // decode triangular block index -> (ti, tj), ti <= tj
    int b = blockIdx.x;
    float nt2 = 2.0f * nt + 1.0f;
    int ti = (int)((nt2 - sqrtf(nt2 * nt2 - 8.0f * (float)b)) * 0.5f);
    if (ti < 0) ti = 0;
    while (ti + 1 < nt && row_start(ti + 1, nt) <= b) ti++;
    while (ti > 0 && row_start(ti, nt) > b) ti--;
    int tj = ti + (b - row_start(ti, nt));

    const float Lx = box[0], Ly = box[1], Lz = box[2];
    const float iLx = 1.0f/Lx, iLy = 1.0f/Ly, iLz = 1.0f/Lz;

    // ---- tile-pair AABB cull (uniform across block, before any sync) ----
    if (ti != tj) {
        float4 bi = g_tbox[ti];
        float4 bj = g_tbox[tj];
        float dxm = fmaxf(fabsf(mic(bi.x - bj.x, Lx, iLx)) - (bi.y + bj.y), 0.0f);
        float dym = fmaxf(fabsf(mic(bi.z - bj.z, Ly, iLy)) - (bi.w + bj.w), 0.0f);
        if (fmaf(dxm, dxm, dym * dym) >= CULL2) return;
    }

    const float s00sq = sigma[0] * sigma[0];
    const float e00x4 = 4.0f * epsilon[0];

    __shared__ float4 sj[JHALF];
    int jbase = tj * ITILE + blockIdx.y * JHALF;
    if ((int)threadIdx.x < JHALF) sj[threadIdx.x] = g_atoms[jbase + threadIdx.x];
    __syncthreads();

    int i = ti * ITILE + threadIdx.x;
    float4 a = g_atoms[i];
    bool iO = (a.w < 0.0f);

    float ec = 0.0f, el = 0.0f;
    if (ti == tj) {
#pragma unroll 8
        for (int t = 0; t < JHALF; ++t) {
            int j = jbase + t;
            pair_term(a, iO, sj[t], j > i, Lx, Ly, Lz, iLx, iLy, iLz, s00sq, e00x4, ec, el);
        }
    } else {
#pragma unroll 8
        for (int t = 0; t < JHALF; ++t) {
            pair_term(a, iO, sj[t], true, Lx, Ly, Lz, iLx, iLy, iLz, s00sq, e00x4, ec, el);
        }
    }

    double e = (double)PREF * (double)ec + (double)el;
    double s = blockReduceD(e);
    if (threadIdx.x == 0 && s != 0.0) atomicAdd(&g_energy, s);
}

// ---------------- kernel 4: structure factors, half k-space ----------------
#define RT_THREADS 128
#define NCHUNK 8

__global__ void k_recip(int N, int CH, const float* __restrict__ box) {
    int hk = blockIdx.x;
    int h, k; hk_decode(hk, h, k);

    const float Lx = box[0], Ly = box[1], Lz = box[2];
    const float twopi = 6.283185307179586f;
    const float gz = twopi / Lz;
    const float kx = twopi * (float)h / Lx;
    const float ky = twopi * (float)k / Ly;

    int base = blockIdx.y * CH;
    int end  = min(N, base + CH);

    float accR[17], accI[17];
#pragma unroll
    for (int l = 0; l < 17; ++l) { accR[l] = 0.0f; accI[l] = 0.0f; }

    for (int i = base + threadIdx.x; i < end; i += 2 * RT_THREADS) {
        float4 a1 = g_atoms[i];
        int ii = i + RT_THREADS;
        float4 a2 = (ii < end) ? g_atoms[ii] : make_float4(0.f, 0.f, 0.f, 0.f);

        float phz1 = gz * a1.z, phz2 = gz * a2.z;
        float s1, c1, d1s, d1c, s2, c2, d2s, d2c;
        sincosf(kx * a1.x + ky * a1.y - 8.0f * phz1, &s1, &c1);
        sincosf(phz1, &d1s, &d1c);
        sincosf(kx * a2.x + ky * a2.y - 8.0f * phz2, &s2, &c2);
        sincosf(phz2, &d2s, &d2c);
        float q1 = a1.w, q2 = a2.w;
#pragma unroll
        for (int l = 0; l < 17; ++l) {
            accR[l] = fmaf(q1, c1, fmaf(q2, c2, accR[l]));
            accI[l] = fmaf(q1, s1, fmaf(q2, s2, accI[l]));
            float n1 = c1 * d1c - s1 * d1s;
            s1 = fmaf(s1, d1c, c1 * d1s); c1 = n1;
            float n2 = c2 * d2c - s2 * d2s;
            s2 = fmaf(s2, d2c, c2 * d2s); c2 = n2;
        }
    }

    __shared__ float shR[RT_THREADS / 32][17], shI[RT_THREADS / 32][17];
    int lane = threadIdx.x & 31;
    int wid  = threadIdx.x >> 5;
#pragma unroll
    for (int l = 0; l < 17; ++l) {
        float r = accR[l], im = accI[l];
#pragma unroll
        for (int o = 16; o > 0; o >>= 1) {
            r  += __shfl_down_sync(0xffffffffu, r,  o);
            im += __shfl_down_sync(0xffffffffu, im, o);
        }
        if (lane == 0) { shR[wid][l] = r; shI[wid][l] = im; }
    }
    __syncthreads();
    if (threadIdx.x < 17) {
        int l = threadIdx.x;
        float R = 0.0f, I = 0.0f;
#pragma unroll
        for (int w = 0; w < RT_THREADS / 32; ++w) { R += shR[w][l]; I += shI[w][l]; }
        atomicAdd(&g_S[hk * 17 + l].x, R);
        atomicAdd(&g_S[hk * 17 + l].y, I);
    }
}

// ---------------- kernel 5: reciprocal energy from S + finalize ----------------
// Single block; float exp (MUFU), double accumulation only. Writes d_out.
__global__ void k_recipE_final(const float* __restrict__ box, float* out) {
    const float Lx = box[0], Ly = box[1], Lz = box[2];
    const float gx = 6.283185307179586f / Lx;
    const float gy = 6.283185307179586f / Ly;
    const float gzf = 6.283185307179586f / Lz;
    double e = 0.0;
    for (int idx = threadIdx.x; idx < NSF; idx += blockDim.x) {
        int hk = idx / 17;
        int l  = idx % 17 - 8;
        int h, k; hk_decode(hk, h, k);
        if (h == 0 && k == 0 && l >= 0) continue;   // k=0 excluded; l>0 via conj
        float2 S = g_S[idx];
        float kxf = gx * h, kyf = gy * k, kzf = gzf * l;
        float k2 = kxf * kxf + kyf * kyf + kzf * kzf;
        float w  = __expf(-k2 * (1.0f / 36.0f)) * __frcp_rn(k2);  // 4*alpha^2 = 36
        float S2 = S.x * S.x + S.y * S.y;
        e += (double)(2.0f * w * S2);               // x2: +-k pair
    }
    double V = (double)Lx * (double)Ly * (double)Lz;
    e *= (double)PREF * (2.0 * 3.141592653589793 / V);
    double s = blockReduceD(e);
    if (threadIdx.x == 0) {
        out[0] = (float)(g_energy + s);
    }
}

// ---------------- launch ----------------
extern "C" void kernel_launch(void* const* d_in, const int* in_sizes, int n_in,
                              void* d_out, int out_size) {
    const float* coords  = (const float*)d_in[0];
    const float* box     = (const float*)d_in[1];
    const int*   bonds   = (const int*)  d_in[2];
    const float* b0      = (const float*)d_in[3];
    const float* kb      = (const float*)d_in[4];
    const int*   angles  = (const int*)  d_in[5];
    const float* th0     = (const float*)d_in[6];
    const float* kth     = (const float*)d_in[7];
    const float* charges = (const float*)d_in[8];
    const float* sigma   = (const float*)d_in[9];
    const float* epsilon = (const float*)d_in[10];
    const int*   cex     = (const int*)  d_in[13];   // coulomb_excl_pairs

    int N   = in_sizes[0] / 3;
    int nb  = in_sizes[2] / 2;
    int na  = in_sizes[5] / 3;
    int nex = in_sizes[13] / 2;

    float* out = (float*)d_out;

    int nt = (N + ITILE - 1) / ITILE;

    int nthr = 256;
    int maxWork = N;
    if (nb  > maxWork) maxWork = nb;
    if (na  > maxWork) maxWork = na;
    if (nex > maxWork) maxWork = nex;

    k_prep<<<nt, ITILE>>>(coords, charges, N, nt);
    k_bonded<<<(maxWork + nthr - 1) / nthr, nthr>>>(coords, box, bonds, b0, kb, nb,
                                                    angles, th0, kth, na,
                                                    cex, charges, nex, N);
    dim3 pg(nt * (nt + 1) / 2, ITILE / JHALF);
    k_pair<<<pg, ITILE>>>(nt, box, sigma, epsilon);

    int CH = (N + NCHUNK - 1) / NCHUNK;
    dim3 rg(NHK, NCHUNK);
    k_recip<<<rg, RT_THREADS>>>(N, CH, box);
    k_recipE_final<<<1, 256>>>(box, out);
}

// round 8
// speedup vs baseline: 2.5802x; 1.5000x over previous
#include <cuda_runtime.h>
#include <math.h>

// ---------------- constants ----------------
#define PREF   138.935456f
#define ALPHA  3.0f
#define CUT2   0.81f          // 0.9^2
#define CULL2  0.8190f        // (0.9 + safety)^2 for conservative tile culling
#define MAXH   8
#define NHK    145            // half k-space (h,k) blocks: 8*17 + 8 + 1
#define NSF    (NHK * 17)     // 2465 stored structure factors

#define ITILE 128
#define JSUB  32
#define MAXN  8192
#define MAXT  (MAXN / ITILE)

__device__ float4 g_atoms[MAXN];   // x,y,z,charge (padded with q=0 copies of last atom)
__device__ float4 g_tbox[MAXT];    // per-tile (cx, hx, cy, hy)
__device__ float2 g_S[NSF];        // structure factors (re, im)
__device__ double g_energy;

// ---------------- reductions ----------------
__device__ __forceinline__ double blockReduceD(double v) {
    __shared__ double sh[32];
    int lane = threadIdx.x & 31;
    int wid  = threadIdx.x >> 5;
#pragma unroll
    for (int o = 16; o > 0; o >>= 1) v += __shfl_down_sync(0xffffffffu, v, o);
    if (lane == 0) sh[wid] = v;
    __syncthreads();
    int nwarp = (blockDim.x + 31) >> 5;
    v = (threadIdx.x < nwarp) ? sh[threadIdx.x] : 0.0;
    if (wid == 0) {
#pragma unroll
        for (int o = 16; o > 0; o >>= 1) v += __shfl_down_sync(0xffffffffu, v, o);
    }
    return v;
}

__device__ __forceinline__ float mic(float d, float L, float invL) {
    return d - L * rintf(d * invL);   // round-half-even, matches jnp.round
}

// (h,k) decode for the half k-space block list
__device__ __forceinline__ void hk_decode(int hk, int &h, int &k) {
    if (hk < 136)      { h = hk / 17 - 8; k = hk % 17 - 8; }  // h = -8..-1, all k
    else if (hk < 144) { h = 0; k = hk - 144; }               // h = 0, k = -8..-1
    else               { h = 0; k = 0; }                      // l < 0 only
}

// ---------------- kernel 1: prep (pack+pad atoms, tile bbox, zero accums) ----------------
__global__ void k_prep(const float* __restrict__ coords,
                       const float* __restrict__ charges, int N, int nt) {
    int i = blockIdx.x * ITILE + threadIdx.x;
    if (i == 0) g_energy = 0.0;
    for (int s = i; s < NSF; s += nt * ITILE) g_S[s] = make_float2(0.0f, 0.0f);

    float4 a;
    if (i < N) a = make_float4(coords[3*i], coords[3*i+1], coords[3*i+2], charges[i]);
    else       a = make_float4(coords[3*(N-1)], coords[3*(N-1)+1], coords[3*(N-1)+2], 0.0f);
    g_atoms[i] = a;

    // tile AABB in x,y
    float mnx = a.x, mxx = a.x, mny = a.y, mxy = a.y;
    int lane = threadIdx.x & 31;
    int wid  = threadIdx.x >> 5;
#pragma unroll
    for (int o = 16; o > 0; o >>= 1) {
        mnx = fminf(mnx, __shfl_down_sync(0xffffffffu, mnx, o));
        mxx = fmaxf(mxx, __shfl_down_sync(0xffffffffu, mxx, o));
        mny = fminf(mny, __shfl_down_sync(0xffffffffu, mny, o));
        mxy = fmaxf(mxy, __shfl_down_sync(0xffffffffu, mxy, o));
    }
    __shared__ float s0[4], s1[4], s2[4], s3[4];
    if (lane == 0) { s0[wid] = mnx; s1[wid] = mxx; s2[wid] = mny; s3[wid] = mxy; }
    __syncthreads();
    if (threadIdx.x == 0) {
        mnx = fminf(fminf(s0[0], s0[1]), fminf(s0[2], s0[3]));
        mxx = fmaxf(fmaxf(s1[0], s1[1]), fmaxf(s1[2], s1[3]));
        mny = fminf(fminf(s2[0], s2[1]), fminf(s2[2], s2[3]));
        mxy = fmaxf(fmaxf(s3[0], s3[1]), fmaxf(s3[2], s3[3]));
        g_tbox[blockIdx.x] = make_float4(0.5f * (mnx + mxx), 0.5f * (mxx - mnx),
                                         0.5f * (mny + mxy), 0.5f * (mxy - mny));
    }
}

// ---------------- kernel 2: bonded + angles + full-Coulomb excl + self ----------------
// k_pair includes intra-molecular pairs with erfc; combined with the reference's
// -qq*erf/r exclusion term this collapses to -qq/r (erf + erfc = 1).
__global__ void k_bonded(const float* __restrict__ coords,
                         const float* __restrict__ box,
                         const int*   __restrict__ bonds,
                         const float* __restrict__ b0,
                         const float* __restrict__ kb, int nb,
                         const int*   __restrict__ angles,
                         const float* __restrict__ th0,
                         const float* __restrict__ kth, int na,
                         const int*   __restrict__ cex,
                         const float* __restrict__ charges, int nex, int N) {
    const float Lx = box[0], Ly = box[1], Lz = box[2];
    const float iLx = 1.0f/Lx, iLy = 1.0f/Ly, iLz = 1.0f/Lz;
    int i = blockIdx.x * blockDim.x + threadIdx.x;
    double e = 0.0;

    if (i < nb) {
        int a = bonds[2*i], b = bonds[2*i+1];
        float dx = mic(coords[3*a+0]-coords[3*b+0], Lx, iLx);
        float dy = mic(coords[3*a+1]-coords[3*b+1], Ly, iLy);
        float dz = mic(coords[3*a+2]-coords[3*b+2], Lz, iLz);
        float r = sqrtf(dx*dx + dy*dy + dz*dz);
        float d = r - b0[i];
        e += 0.5 * (double)(kb[i] * d * d);
    }
    if (i < na) {
        int a0 = angles[3*i], a1 = angles[3*i+1], a2 = angles[3*i+2];
        float v1x = mic(coords[3*a0+0]-coords[3*a1+0], Lx, iLx);
        float v1y = mic(coords[3*a0+1]-coords[3*a1+1], Ly, iLy);
        float v1z = mic(coords[3*a0+2]-coords[3*a1+2], Lz, iLz);
        float v2x = mic(coords[3*a2+0]-coords[3*a1+0], Lx, iLx);
        float v2y = mic(coords[3*a2+1]-coords[3*a1+1], Ly, iLy);
        float v2z = mic(coords[3*a2+2]-coords[3*a1+2], Lz, iLz);
        float n1 = sqrtf(v1x*v1x + v1y*v1y + v1z*v1z);
        float n2 = sqrtf(v2x*v2x + v2y*v2y + v2z*v2z);
        float ct = (v1x*v2x + v1y*v2y + v1z*v2z) / (n1 * n2);
        ct = fminf(fmaxf(ct, -1.0f + 1e-7f), 1.0f - 1e-7f);
        float th = acosf(ct);
        float d = th - th0[i];
        e += 0.5 * (double)(kth[i] * d * d);
    }
    if (i < nex) {   // -PREF * q_a q_b / r   (erf + erfc merged)
        int a = cex[2*i], b = cex[2*i+1];
        float dx = mic(coords[3*a+0]-coords[3*b+0], Lx, iLx);
        float dy = mic(coords[3*a+1]-coords[3*b+1], Ly, iLy);
        float dz = mic(coords[3*a+2]-coords[3*b+2], Lz, iLz);
        float r = sqrtf(dx*dx + dy*dy + dz*dz);
        float qx = charges[a] * charges[b];
        e -= (double)(PREF * qx / r);
    }
    if (i < N) {     // self: -PREF * alpha/sqrt(pi) * q^2
        float q = charges[i];
        e -= (double)(PREF * (ALPHA * 0.5641895835477563f) * q * q);
    }

    double s = blockReduceD(e);
    if (threadIdx.x == 0 && s != 0.0) atomicAdd(&g_energy, s);
}

// ---------------- kernel 3: real-space nonbonded ----------------
// Triangular 128x128 tile pairs; 128 threads (1 i-atom each); j-tile split in
// four 32-atom quarters over blockIdx.y. Tile-pair AABB culling, early exit.
__device__ __forceinline__ int row_start(int ti, int nt) {
    return ti * (2 * nt - ti + 1) / 2;
}

__device__ __forceinline__ void pair_term(
    float4 a, bool iO, float4 b, bool take,
    float Lx, float Ly, float Lz, float iLx, float iLy, float iLz,
    float s00sq, float e00x4, float &ec, float &el)
{
    float dx = mic(a.x - b.x, Lx, iLx);
    float dy = mic(a.y - b.y, Ly, iLy);
    float dz = mic(a.z - b.z, Lz, iLz);
    float r2 = fmaf(dx, dx, fmaf(dy, dy, dz * dz));
    r2 = fmaxf(r2, 1e-6f);                      // guards padded-atom r2=0
    if (take && r2 < CUT2) {
        float rinv = rsqrtf(r2);
        float x    = ALPHA * r2 * rinv;          // alpha * r
        // erfc(x) via A&S 7.1.26 (|abs err| <= 1.5e-7)
        float tt = __fdividef(1.0f, fmaf(0.3275911f, x, 1.0f));
        float p  = fmaf(1.061405429f, tt, -1.453152027f);
        p = fmaf(p, tt, 1.421413741f);
        p = fmaf(p, tt, -0.284496736f);
        p = fmaf(p, tt, 0.254829592f);
        p = p * tt;
        float ef = p * __expf(-x * x);
        ec = fmaf(a.w * b.w, ef * rinv, ec);
        float eps4 = (iO && b.w < 0.0f) ? e00x4 : 0.0f;   // O-O only
        float sr2  = s00sq * (rinv * rinv);
        float s6   = sr2 * sr2 * sr2;
        el = fmaf(eps4, s6 * s6 - s6, el);
    }
}

__global__ void k_pair(int nt, const float* __restrict__ box,
                       const float* __restrict__ sigma,
                       const float* __restrict__ epsilon) {
    // decode triangular block index -> (ti, tj), ti <= tj
    int b = blockIdx.x;
    float nt2 = 2.0f * nt + 1.0f;
    int ti = (int)((nt2 - sqrtf(nt2 * nt2 - 8.0f * (float)b)) * 0.5f);
    if (ti < 0) ti = 0;
    while (ti + 1 < nt && row_start(ti + 1, nt) <= b) ti++;
    while (ti > 0 && row_start(ti, nt) > b) ti--;
    int tj = ti + (b - row_start(ti, nt));

    const float Lx = box[0], Ly = box[1], Lz = box[2];
    const float iLx = 1.0f/Lx, iLy = 1.0f/Ly, iLz = 1.0f/Lz;

    // ---- tile-pair AABB cull (uniform across block, before any sync) ----
    if (ti != tj) {
        float4 bi = g_tbox[ti];
        float4 bj = g_tbox[tj];
        float dxm = fmaxf(fabsf(mic(bi.x - bj.x, Lx, iLx)) - (bi.y + bj.y), 0.0f);
        float dym = fmaxf(fabsf(mic(bi.z - bj.z, Ly, iLy)) - (bi.w + bj.w), 0.0f);
        if (fmaf(dxm, dxm, dym * dym) >= CULL2) return;
    }

    const float s00sq = sigma[0] * sigma[0];
    const float e00x4 = 4.0f * epsilon[0];

    __shared__ float4 sj[JSUB];
    int jbase = tj * ITILE + blockIdx.y * JSUB;
    if ((int)threadIdx.x < JSUB) sj[threadIdx.x] = g_atoms[jbase + threadIdx.x];
    __syncthreads();

    int i = ti * ITILE + threadIdx.x;
    float4 a = g_atoms[i];
    bool iO = (a.w < 0.0f);

    float ec = 0.0f, el = 0.0f;
    if (ti == tj) {
#pragma unroll 8
        for (int t = 0; t < JSUB; ++t) {
            int j = jbase + t;
            pair_term(a, iO, sj[t], j > i, Lx, Ly, Lz, iLx, iLy, iLz, s00sq, e00x4, ec, el);
        }
    } else {
#pragma unroll 8
        for (int t = 0; t < JSUB; ++t) {
            pair_term(a, iO, sj[t], true, Lx, Ly, Lz, iLx, iLy, iLz, s00sq, e00x4, ec, el);
        }
    }

    double e = (double)PREF * (double)ec + (double)el;
    double s = blockReduceD(e);
    if (threadIdx.x == 0 && s != 0.0) atomicAdd(&g_energy, s);
}

// ---------------- kernel 4: structure factors, half k-space ----------------
#define RT_THREADS 128
#define NCHUNK 8

__global__ void k_recip(int N, int CH, const float* __restrict__ box) {
    int hk = blockIdx.x;
    int h, k; hk_decode(hk, h, k);

    const float Lx = box[0], Ly = box[1], Lz = box[2];
    const float twopi = 6.283185307179586f;
    const float gz = twopi / Lz;
    const float kx = twopi * (float)h / Lx;
    const float ky = twopi * (float)k / Ly;

    int base = blockIdx.y * CH;
    int end  = min(N, base + CH);

    float accR[17], accI[17];
#pragma unroll
    for (int l = 0; l < 17; ++l) { accR[l] = 0.0f; accI[l] = 0.0f; }

    for (int i = base + threadIdx.x; i < end; i += 2 * RT_THREADS) {
        float4 a1 = g_atoms[i];
        int ii = i + RT_THREADS;
        float4 a2 = (ii < end) ? g_atoms[ii] : make_float4(0.f, 0.f, 0.f, 0.f);

        float phz1 = gz * a1.z, phz2 = gz * a2.z;
        float s1, c1, d1s, d1c, s2, c2, d2s, d2c;
        sincosf(kx * a1.x + ky * a1.y - 8.0f * phz1, &s1, &c1);
        sincosf(phz1, &d1s, &d1c);
        sincosf(kx * a2.x + ky * a2.y - 8.0f * phz2, &s2, &c2);
        sincosf(phz2, &d2s, &d2c);
        float q1 = a1.w, q2 = a2.w;
#pragma unroll
        for (int l = 0; l < 17; ++l) {
            accR[l] = fmaf(q1, c1, fmaf(q2, c2, accR[l]));
            accI[l] = fmaf(q1, s1, fmaf(q2, s2, accI[l]));
            float n1 = c1 * d1c - s1 * d1s;
            s1 = fmaf(s1, d1c, c1 * d1s); c1 = n1;
            float n2 = c2 * d2c - s2 * d2s;
            s2 = fmaf(s2, d2c, c2 * d2s); c2 = n2;
        }
    }

    __shared__ float shR[RT_THREADS / 32][17], shI[RT_THREADS / 32][17];
    int lane = threadIdx.x & 31;
    int wid  = threadIdx.x >> 5;
#pragma unroll
    for (int l = 0; l < 17; ++l) {
        float r = accR[l], im = accI[l];
#pragma unroll
        for (int o = 16; o > 0; o >>= 1) {
            r  += __shfl_down_sync(0xffffffffu, r,  o);
            im += __shfl_down_sync(0xffffffffu, im, o);
        }
        if (lane == 0) { shR[wid][l] = r; shI[wid][l] = im; }
    }
    __syncthreads();
    if (threadIdx.x < 17) {
        int l = threadIdx.x;
        float R = 0.0f, I = 0.0f;
#pragma unroll
        for (int w = 0; w < RT_THREADS / 32; ++w) { R += shR[w][l]; I += shI[w][l]; }
        atomicAdd(&g_S[hk * 17 + l].x, R);
        atomicAdd(&g_S[hk * 17 + l].y, I);
    }
}

// ---------------- kernel 5: reciprocal energy from S + finalize ----------------
__global__ void k_recipE_final(const float* __restrict__ box, float* out) {
    const float Lx = box[0], Ly = box[1], Lz = box[2];
    const float gx = 6.283185307179586f / Lx;
    const float gy = 6.283185307179586f / Ly;
    const float gzf = 6.283185307179586f / Lz;
    double e = 0.0;
    for (int idx = threadIdx.x; idx < NSF; idx += blockDim.x) {
        int hk = idx / 17;
        int l  = idx % 17 - 8;
        int h, k; hk_decode(hk, h, k);
        if (h == 0 && k == 0 && l >= 0) continue;   // k=0 excluded; l>0 via conj
        float2 S = g_S[idx];
        float kxf = gx * h, kyf = gy * k, kzf = gzf * l;
        float k2 = kxf * kxf + kyf * kyf + kzf * kzf;
        float w  = __expf(-k2 * (1.0f / 36.0f)) * __frcp_rn(k2);  // 4*alpha^2 = 36
        float S2 = S.x * S.x + S.y * S.y;
        e += (double)(2.0f * w * S2);               // x2: +-k pair
    }
    double V = (double)Lx * (double)Ly * (double)Lz;
    e *= (double)PREF * (2.0 * 3.141592653589793 / V);
    double s = blockReduceD(e);
    if (threadIdx.x == 0) {
        out[0] = (float)(g_energy + s);
    }
}

// ---------------- launch ----------------
extern "C" void kernel_launch(void* const* d_in, const int* in_sizes, int n_in,
                              void* d_out, int out_size) {
    const float* coords  = (const float*)d_in[0];
    const float* box     = (const float*)d_in[1];
    const int*   bonds   = (const int*)  d_in[2];
    const float* b0      = (const float*)d_in[3];
    const float* kb      = (const float*)d_in[4];
    const int*   angles  = (const int*)  d_in[5];
    const float* th0     = (const float*)d_in[6];
    const float* kth     = (const float*)d_in[7];
    const float* charges = (const float*)d_in[8];
    const float* sigma   = (const float*)d_in[9];
    const float* epsilon = (const float*)d_in[10];
    const int*   cex     = (const int*)  d_in[13];   // coulomb_excl_pairs

    int N   = in_sizes[0] / 3;
    int nb  = in_sizes[2] / 2;
    int na  = in_sizes[5] / 3;
    int nex = in_sizes[13] / 2;

    float* out = (float*)d_out;

    int nt = (N + ITILE - 1) / ITILE;

    int nthr = 256;
    int maxWork = N;
    if (nb  > maxWork) maxWork = nb;
    if (na  > maxWork) maxWork = na;
    if (nex > maxWork) maxWork = nex;

    // lazily-created side streams + events for fork/join inside graph capture
    static cudaStream_t sA = 0, sB = 0;
    static cudaEvent_t  evRoot = 0, evA = 0, evB = 0;
    if (sA == 0) {
        cudaStreamCreateWithFlags(&sA, cudaStreamNonBlocking);
        cudaStreamCreateWithFlags(&sB, cudaStreamNonBlocking);
        cudaEventCreateWithFlags(&evRoot, cudaEventDisableTiming);
        cudaEventCreateWithFlags(&evA, cudaEventDisableTiming);
        cudaEventCreateWithFlags(&evB, cudaEventDisableTiming);
    }

    // root: prep on the captured (default) stream
    k_prep<<<nt, ITILE>>>(coords, charges, N, nt);
    cudaEventRecord(evRoot, 0);
    cudaStreamWaitEvent(sA, evRoot, 0);
    cudaStreamWaitEvent(sB, evRoot, 0);

    // fork: k_pair on sA, k_recip on sB, bonded on default — all independent
    dim3 pg(nt * (nt + 1) / 2, ITILE / JSUB);
    k_pair<<<pg, ITILE, 0, sA>>>(nt, box, sigma, epsilon);

    int CH = (N + NCHUNK - 1) / NCHUNK;
    dim3 rg(NHK, NCHUNK);
    k_recip<<<rg, RT_THREADS, 0, sB>>>(N, CH, box);

    k_bonded<<<(maxWork + nthr - 1) / nthr, nthr>>>(coords, box, bonds, b0, kb, nb,
                                                    angles, th0, kth, na,
                                                    cex, charges, nex, N);

    // join: recipE_final needs g_energy (bonded+pair) and g_S (recip)
    cudaEventRecord(evA, sA);
    cudaEventRecord(evB, sB);
    cudaStreamWaitEvent(0, evA, 0);
    cudaStreamWaitEvent(0, evB, 0);
    k_recipE_final<<<1, 256>>>(box, out);
}

// round 9
// speedup vs baseline: 2.6739x; 1.0363x over previous
#include <cuda_runtime.h>
#include <math.h>

// ---------------- constants ----------------
#define PREF   138.935456f
#define ALPHA  3.0f
#define CUT2   0.81f          // 0.9^2
#define CULL2  0.8190f        // (0.9 + safety)^2 for conservative tile culling
#define MAXH   8
#define NHK    145            // half k-space (h,k) blocks: 8*17 + 8 + 1
#define NSF    (NHK * 17)     // 2465 stored structure factors

#define ITILE 128
#define JSUB  32
#define MAXN  8192
#define MAXT  (MAXN / ITILE)

__device__ float4 g_atoms[MAXN];   // x,y,z,charge (padded with q=0 copies of last atom)
__device__ float4 g_tbox[MAXT];    // per-tile (cx, hx, cy, hy)
__device__ float2 g_S[NSF];        // structure factors (re, im)
__device__ double g_energy;

// ---------------- reductions ----------------
__device__ __forceinline__ double blockReduceD(double v) {
    __shared__ double sh[32];
    int lane = threadIdx.x & 31;
    int wid  = threadIdx.x >> 5;
#pragma unroll
    for (int o = 16; o > 0; o >>= 1) v += __shfl_down_sync(0xffffffffu, v, o);
    if (lane == 0) sh[wid] = v;
    __syncthreads();
    int nwarp = (blockDim.x + 31) >> 5;
    v = (threadIdx.x < nwarp) ? sh[threadIdx.x] : 0.0;
    if (wid == 0) {
#pragma unroll
        for (int o = 16; o > 0; o >>= 1) v += __shfl_down_sync(0xffffffffu, v, o);
    }
    return v;
}

__device__ __forceinline__ float mic(float d, float L, float invL) {
    return d - L * rintf(d * invL);   // round-half-even, matches jnp.round
}

// (h,k) decode for the half k-space block list
__device__ __forceinline__ void hk_decode(int hk, int &h, int &k) {
    if (hk < 136)      { h = hk / 17 - 8; k = hk % 17 - 8; }  // h = -8..-1, all k
    else if (hk < 144) { h = 0; k = hk - 144; }               // h = 0, k = -8..-1
    else               { h = 0; k = 0; }                      // l < 0 only
}

// ---------------- kernel 1: prep (pack+pad atoms, tile bbox, zero accums) ----------------
__global__ void k_prep(const float* __restrict__ coords,
                       const float* __restrict__ charges, int N, int nt) {
    int i = blockIdx.x * ITILE + threadIdx.x;
    if (i == 0) g_energy = 0.0;
    for (int s = i; s < NSF; s += nt * ITILE) g_S[s] = make_float2(0.0f, 0.0f);

    float4 a;
    if (i < N) a = make_float4(coords[3*i], coords[3*i+1], coords[3*i+2], charges[i]);
    else       a = make_float4(coords[3*(N-1)], coords[3*(N-1)+1], coords[3*(N-1)+2], 0.0f);
    g_atoms[i] = a;

    // tile AABB in x,y
    float mnx = a.x, mxx = a.x, mny = a.y, mxy = a.y;
    int lane = threadIdx.x & 31;
    int wid  = threadIdx.x >> 5;
#pragma unroll
    for (int o = 16; o > 0; o >>= 1) {
        mnx = fminf(mnx, __shfl_down_sync(0xffffffffu, mnx, o));
        mxx = fmaxf(mxx, __shfl_down_sync(0xffffffffu, mxx, o));
        mny = fminf(mny, __shfl_down_sync(0xffffffffu, mny, o));
        mxy = fmaxf(mxy, __shfl_down_sync(0xffffffffu, mxy, o));
    }
    __shared__ float s0[4], s1[4], s2[4], s3[4];
    if (lane == 0) { s0[wid] = mnx; s1[wid] = mxx; s2[wid] = mny; s3[wid] = mxy; }
    __syncthreads();
    if (threadIdx.x == 0) {
        mnx = fminf(fminf(s0[0], s0[1]), fminf(s0[2], s0[3]));
        mxx = fmaxf(fmaxf(s1[0], s1[1]), fmaxf(s1[2], s1[3]));
        mny = fminf(fminf(s2[0], s2[1]), fminf(s2[2], s2[3]));
        mxy = fmaxf(fmaxf(s3[0], s3[1]), fmaxf(s3[2], s3[3]));
        g_tbox[blockIdx.x] = make_float4(0.5f * (mnx + mxx), 0.5f * (mxx - mnx),
                                         0.5f * (mny + mxy), 0.5f * (mxy - mny));
    }
}

// ---------------- kernel 2: bonded, one task per thread ----------------
// task t in [0,nb): bond; [nb,nb+na): angle; then excl; then self.
// Reads packed g_atoms (must run after k_prep).
// Exclusion term is -qq/r (erf+erfc merged; k_pair adds erfc for these pairs).
__global__ void k_bonded(const float* __restrict__ box,
                         const int*   __restrict__ bonds,
                         const float* __restrict__ b0,
                         const float* __restrict__ kb, int nb,
                         const int*   __restrict__ angles,
                         const float* __restrict__ th0,
                         const float* __restrict__ kth, int na,
                         const int*   __restrict__ cex, int nex, int N) {
    const float Lx = box[0], Ly = box[1], Lz = box[2];
    const float iLx = 1.0f/Lx, iLy = 1.0f/Ly, iLz = 1.0f/Lz;
    int t = blockIdx.x * blockDim.x + threadIdx.x;
    double e = 0.0;

    if (t < nb) {
        int a = bonds[2*t], b = bonds[2*t+1];
        float4 A = g_atoms[a], B = g_atoms[b];
        float dx = mic(A.x - B.x, Lx, iLx);
        float dy = mic(A.y - B.y, Ly, iLy);
        float dz = mic(A.z - B.z, Lz, iLz);
        float r = sqrtf(dx*dx + dy*dy + dz*dz);
        float d = r - b0[t];
        e = 0.5 * (double)(kb[t] * d * d);
    } else if (t < nb + na) {
        int u = t - nb;
        int a0 = angles[3*u], a1 = angles[3*u+1], a2 = angles[3*u+2];
        float4 A = g_atoms[a0], B = g_atoms[a1], C = g_atoms[a2];
        float v1x = mic(A.x - B.x, Lx, iLx);
        float v1y = mic(A.y - B.y, Ly, iLy);
        float v1z = mic(A.z - B.z, Lz, iLz);
        float v2x = mic(C.x - B.x, Lx, iLx);
        float v2y = mic(C.y - B.y, Ly, iLy);
        float v2z = mic(C.z - B.z, Lz, iLz);
        float n1 = sqrtf(v1x*v1x + v1y*v1y + v1z*v1z);
        float n2 = sqrtf(v2x*v2x + v2y*v2y + v2z*v2z);
        float ct = (v1x*v2x + v1y*v2y + v1z*v2z) / (n1 * n2);
        ct = fminf(fmaxf(ct, -1.0f + 1e-7f), 1.0f - 1e-7f);
        float th = acosf(ct);
        float d = th - th0[u];
        e = 0.5 * (double)(kth[u] * d * d);
    } else if (t < nb + na + nex) {
        int u = t - nb - na;
        int a = cex[2*u], b = cex[2*u+1];
        float4 A = g_atoms[a], B = g_atoms[b];
        float dx = mic(A.x - B.x, Lx, iLx);
        float dy = mic(A.y - B.y, Ly, iLy);
        float dz = mic(A.z - B.z, Lz, iLz);
        float r = sqrtf(dx*dx + dy*dy + dz*dz);
        e = -(double)(PREF * A.w * B.w / r);
    } else if (t < nb + na + nex + N) {
        int u = t - nb - na - nex;
        float q = g_atoms[u].w;
        e = -(double)(PREF * (ALPHA * 0.5641895835477563f) * q * q);
    }

    double s = blockReduceD(e);
    if (threadIdx.x == 0 && s != 0.0) atomicAdd(&g_energy, s);
}

// ---------------- kernel 3: real-space nonbonded ----------------
// Triangular 128x128 tile pairs; 128 threads (1 i-atom each); j-tile split in
// four 32-atom quarters over blockIdx.y. Tile-pair AABB culling, early exit.
__device__ __forceinline__ int row_start(int ti, int nt) {
    return ti * (2 * nt - ti + 1) / 2;
}

__device__ __forceinline__ void pair_term(
    float4 a, bool iO, float4 b, bool take,
    float Lx, float Ly, float Lz, float iLx, float iLy, float iLz,
    float s00sq, float e00x4, float &ec, float &el)
{
    float dx = mic(a.x - b.x, Lx, iLx);
    float dy = mic(a.y - b.y, Ly, iLy);
    float dz = mic(a.z - b.z, Lz, iLz);
    float r2 = fmaf(dx, dx, fmaf(dy, dy, dz * dz));
    r2 = fmaxf(r2, 1e-6f);                      // guards padded-atom r2=0
    if (take && r2 < CUT2) {
        float rinv = rsqrtf(r2);
        float x    = ALPHA * r2 * rinv;          // alpha * r
        // erfc(x) via A&S 7.1.26 (|abs err| <= 1.5e-7)
        float tt = __fdividef(1.0f, fmaf(0.3275911f, x, 1.0f));
        float p  = fmaf(1.061405429f, tt, -1.453152027f);
        p = fmaf(p, tt, 1.421413741f);
        p = fmaf(p, tt, -0.284496736f);
        p = fmaf(p, tt, 0.254829592f);
        p = p * tt;
        float ef = p * __expf(-x * x);
        ec = fmaf(a.w * b.w, ef * rinv, ec);
        float eps4 = (iO && b.w < 0.0f) ? e00x4 : 0.0f;   // O-O only
        float sr2  = s00sq * (rinv * rinv);
        float s6   = sr2 * sr2 * sr2;
        el = fmaf(eps4, s6 * s6 - s6, el);
    }
}

__global__ void k_pair(int nt, const float* __restrict__ box,
                       const float* __restrict__ sigma,
                       const float* __restrict__ epsilon) {
    // decode triangular block index -> (ti, tj), ti <= tj
    int b = blockIdx.x;
    float nt2 = 2.0f * nt + 1.0f;
    int ti = (int)((nt2 - sqrtf(nt2 * nt2 - 8.0f * (float)b)) * 0.5f);
    if (ti < 0) ti = 0;
    while (ti + 1 < nt && row_start(ti + 1, nt) <= b) ti++;
    while (ti > 0 && row_start(ti, nt) > b) ti--;
    int tj = ti + (b - row_start(ti, nt));

    const float Lx = box[0], Ly = box[1], Lz = box[2];
    const float iLx = 1.0f/Lx, iLy = 1.0f/Ly, iLz = 1.0f/Lz;

    // ---- tile-pair AABB cull (uniform across block, before any sync) ----
    if (ti != tj) {
        float4 bi = g_tbox[ti];
        float4 bj = g_tbox[tj];
        float dxm = fmaxf(fabsf(mic(bi.x - bj.x, Lx, iLx)) - (bi.y + bj.y), 0.0f);
        float dym = fmaxf(fabsf(mic(bi.z - bj.z, Ly, iLy)) - (bi.w + bj.w), 0.0f);
        if (fmaf(dxm, dxm, dym * dym) >= CULL2) return;
    }

    const float s00sq = sigma[0] * sigma[0];
    const float e00x4 = 4.0f * epsilon[0];

    __shared__ float4 sj[JSUB];
    int jbase = tj * ITILE + blockIdx.y * JSUB;
    if ((int)threadIdx.x < JSUB) sj[threadIdx.x] = g_atoms[jbase + threadIdx.x];
    __syncthreads();

    int i = ti * ITILE + threadIdx.x;
    float4 a = g_atoms[i];
    bool iO = (a.w < 0.0f);

    float ec = 0.0f, el = 0.0f;
    if (ti == tj) {
#pragma unroll 8
        for (int t = 0; t < JSUB; ++t) {
            int j = jbase + t;
            pair_term(a, iO, sj[t], j > i, Lx, Ly, Lz, iLx, iLy, iLz, s00sq, e00x4, ec, el);
        }
    } else {
#pragma unroll 8
        for (int t = 0; t < JSUB; ++t) {
            pair_term(a, iO, sj[t], true, Lx, Ly, Lz, iLx, iLy, iLz, s00sq, e00x4, ec, el);
        }
    }

    double e = (double)PREF * (double)ec + (double)el;
    double s = blockReduceD(e);
    if (threadIdx.x == 0 && s != 0.0) atomicAdd(&g_energy, s);
}

// ---------------- kernel 4: structure factors, half k-space ----------------
// Fractional-coordinate phases wrapped to [0,2pi) so __sincosf (MUFU fast
// path) is both fast and accurate. 17 l values via complex rotation; two
// independent rotation chains per thread (ILP).
#define RT_THREADS 128
#define NCHUNK 8

__global__ void k_recip(int N, int CH, const float* __restrict__ box) {
    int hk = blockIdx.x;
    int h, k; hk_decode(hk, h, k);

    const float Lx = box[0], Ly = box[1], Lz = box[2];
    const float twopi = 6.283185307179586f;
    const float iLx = 1.0f/Lx, iLy = 1.0f/Ly, iLz = 1.0f/Lz;
    const float fh = (float)h, fk = (float)k;

    int base = blockIdx.y * CH;
    int end  = min(N, base + CH);

    float accR[17], accI[17];
#pragma unroll
    for (int l = 0; l < 17; ++l) { accR[l] = 0.0f; accI[l] = 0.0f; }

    for (int i = base + threadIdx.x; i < end; i += 2 * RT_THREADS) {
        float4 a1 = g_atoms[i];
        int ii = i + RT_THREADS;
        float4 a2 = (ii < end) ? g_atoms[ii] : make_float4(0.f, 0.f, 0.f, 0.f);

        // fractional coords -> wrapped phases in [0, 2pi)
        float uz1 = a1.z * iLz, uz2 = a2.z * iLz;
        float t1 = fh * (a1.x * iLx) + fk * (a1.y * iLy) - 8.0f * uz1;
        float t2 = fh * (a2.x * iLx) + fk * (a2.y * iLy) - 8.0f * uz2;
        t1 -= floorf(t1);
        t2 -= floorf(t2);

        float s1, c1, d1s, d1c, s2, c2, d2s, d2c;
        __sincosf(twopi * t1, &s1, &c1);
        __sincosf(twopi * uz1, &d1s, &d1c);
        __sincosf(twopi * t2, &s2, &c2);
        __sincosf(twopi * uz2, &d2s, &d2c);
        float q1 = a1.w, q2 = a2.w;
#pragma unroll
        for (int l = 0; l < 17; ++l) {
            accR[l] = fmaf(q1, c1, fmaf(q2, c2, accR[l]));
            accI[l] = fmaf(q1, s1, fmaf(q2, s2, accI[l]));
            float n1 = c1 * d1c - s1 * d1s;
            s1 = fmaf(s1, d1c, c1 * d1s); c1 = n1;
            float n2 = c2 * d2c - s2 * d2s;
            s2 = fmaf(s2, d2c, c2 * d2s); c2 = n2;
        }
    }

    __shared__ float shR[RT_THREADS / 32][17], shI[RT_THREADS / 32][17];
    int lane = threadIdx.x & 31;
    int wid  = threadIdx.x >> 5;
#pragma unroll
    for (int l = 0; l < 17; ++l) {
        float r = accR[l], im = accI[l];
#pragma unroll
        for (int o = 16; o > 0; o >>= 1) {
            r  += __shfl_down_sync(0xffffffffu, r,  o);
            im += __shfl_down_sync(0xffffffffu, im, o);
        }
        if (lane == 0) { shR[wid][l] = r; shI[wid][l] = im; }
    }
    __syncthreads();
    if (threadIdx.x < 17) {
        int l = threadIdx.x;
        float R = 0.0f, I = 0.0f;
#pragma unroll
        for (int w = 0; w < RT_THREADS / 32; ++w) { R += shR[w][l]; I += shI[w][l]; }
        atomicAdd(&g_S[hk * 17 + l].x, R);
        atomicAdd(&g_S[hk * 17 + l].y, I);
    }
}

// ---------------- kernel 5: reciprocal energy from S + finalize ----------------
__global__ void k_recipE_final(const float* __restrict__ box, float* out) {
    const float Lx = box[0], Ly = box[1], Lz = box[2];
    const float gx = 6.283185307179586f / Lx;
    const float gy = 6.283185307179586f / Ly;
    const float gzf = 6.283185307179586f / Lz;
    double e = 0.0;
    for (int idx = threadIdx.x; idx < NSF; idx += blockDim.x) {
        int hk = idx / 17;
        int l  = idx % 17 - 8;
        int h, k; hk_decode(hk, h, k);
        if (h == 0 && k == 0 && l >= 0) continue;   // k=0 excluded; l>0 via conj
        float2 S = g_S[idx];
        float kxf = gx * h, kyf = gy * k, kzf = gzf * l;
        float k2 = kxf * kxf + kyf * kyf + kzf * kzf;
        float w  = __expf(-k2 * (1.0f / 36.0f)) * __frcp_rn(k2);  // 4*alpha^2 = 36
        float S2 = S.x * S.x + S.y * S.y;
        e += (double)(2.0f * w * S2);               // x2: +-k pair
    }
    double V = (double)Lx * (double)Ly * (double)Lz;
    e *= (double)PREF * (2.0 * 3.141592653589793 / V);
    double s = blockReduceD(e);
    if (threadIdx.x == 0) {
        out[0] = (float)(g_energy + s);
    }
}

// ---------------- launch ----------------
extern "C" void kernel_launch(void* const* d_in, const int* in_sizes, int n_in,
                              void* d_out, int out_size) {
    const float* coords  = (const float*)d_in[0];
    const float* box     = (const float*)d_in[1];
    const int*   bonds   = (const int*)  d_in[2];
    const float* b0      = (const float*)d_in[3];
    const float* kb      = (const float*)d_in[4];
    const int*   angles  = (const int*)  d_in[5];
    const float* th0     = (const float*)d_in[6];
    const float* kth     = (const float*)d_in[7];
    const float* charges = (const float*)d_in[8];
    const float* sigma   = (const float*)d_in[9];
    const float* epsilon = (const float*)d_in[10];
    const int*   cex     = (const int*)  d_in[13];   // coulomb_excl_pairs

    int N   = in_sizes[0] / 3;
    int nb  = in_sizes[2] / 2;
    int na  = in_sizes[5] / 3;
    int nex = in_sizes[13] / 2;

    float* out = (float*)d_out;

    int nt = (N + ITILE - 1) / ITILE;

    // lazily-created side streams + events for fork/join inside graph capture
    static cudaStream_t sA = 0, sB = 0;
    static cudaEvent_t  evRoot = 0, evA = 0, evB = 0;
    if (sA == 0) {
        cudaStreamCreateWithFlags(&sA, cudaStreamNonBlocking);
        cudaStreamCreateWithFlags(&sB, cudaStreamNonBlocking);
        cudaEventCreateWithFlags(&evRoot, cudaEventDisableTiming);
        cudaEventCreateWithFlags(&evA, cudaEventDisableTiming);
        cudaEventCreateWithFlags(&evB, cudaEventDisableTiming);
    }

    // root: prep on the captured (default) stream
    k_prep<<<nt, ITILE>>>(coords, charges, N, nt);
    cudaEventRecord(evRoot, 0);
    cudaStreamWaitEvent(sA, evRoot, 0);
    cudaStreamWaitEvent(sB, evRoot, 0);

    // fork: k_pair on sA, k_recip on sB, bonded on default — all independent
    dim3 pg(nt * (nt + 1) / 2, ITILE / JSUB);
    k_pair<<<pg, ITILE, 0, sA>>>(nt, box, sigma, epsilon);

    int CH = (N + NCHUNK - 1) / NCHUNK;
    dim3 rg(NHK, NCHUNK);
    k_recip<<<rg, RT_THREADS, 0, sB>>>(N, CH, box);

    int ntasks = nb + na + nex + N;
    k_bonded<<<(ntasks + 255) / 256, 256>>>(box, bonds, b0, kb, nb,
                                            angles, th0, kth, na,
                                            cex, nex, N);

    // join: recipE_final needs g_energy (bonded+pair) and g_S (recip)
    cudaEventRecord(evA, sA);
    cudaEventRecord(evB, sB);
    cudaStreamWaitEvent(0, evA, 0);
    cudaStreamWaitEvent(0, evB, 0);
    k_recipE_final<<<1, 256>>>(box, out);
}